// round 17
// baseline (speedup 1.0000x reference)
#include <cuda_runtime.h>
#include <cuda_bf16.h>
#include <cstdint>

#define B_ 4
#define T_ 2048
#define C_ 1024
#define H_ 16
#define D_ 64
#define M_ (B_*T_)   // 8192

// bf16 hi/lo splits: inputs (x, W) and projected q/k/v
__device__ __nv_bfloat16 g_xh[M_*C_];
__device__ __nv_bfloat16 g_xl[M_*C_];
__device__ __nv_bfloat16 g_wh[3*C_*C_];
__device__ __nv_bfloat16 g_wl[3*C_*C_];
__device__ __nv_bfloat16 g_qh[M_*C_], g_ql[M_*C_];   // q pre-scaled by 1/8
__device__ __nv_bfloat16 g_kh[M_*C_], g_kl[M_*C_];
__device__ __nv_bfloat16 g_vh[M_*C_], g_vl[M_*C_];

// ---------------------------------------------------------------- helpers
__device__ __forceinline__ void mma16816(float* c, const uint32_t* a, const uint32_t* b) {
    asm volatile("mma.sync.aligned.m16n8k16.row.col.f32.bf16.bf16.f32 "
        "{%0,%1,%2,%3}, {%4,%5,%6,%7}, {%8,%9}, {%0,%1,%2,%3};"
        : "+f"(c[0]), "+f"(c[1]), "+f"(c[2]), "+f"(c[3])
        : "r"(a[0]), "r"(a[1]), "r"(a[2]), "r"(a[3]), "r"(b[0]), "r"(b[1]));
}
__device__ __forceinline__ void ldsm4(uint32_t* r, uint32_t a) {
    asm volatile("ldmatrix.sync.aligned.m8n8.x4.shared.b16 {%0,%1,%2,%3}, [%4];"
        : "=r"(r[0]), "=r"(r[1]), "=r"(r[2]), "=r"(r[3]) : "r"(a));
}
__device__ __forceinline__ void ldsm4t(uint32_t* r, uint32_t a) {
    asm volatile("ldmatrix.sync.aligned.m8n8.x4.trans.shared.b16 {%0,%1,%2,%3}, [%4];"
        : "=r"(r[0]), "=r"(r[1]), "=r"(r[2]), "=r"(r[3]) : "r"(a));
}
__device__ __forceinline__ uint32_t smem_u32(const void* p) {
    uint32_t a;
    asm("{ .reg .u64 t; cvta.to.shared.u64 t, %1; cvt.u32.u64 %0, t; }"
        : "=r"(a) : "l"(p));
    return a;
}
__device__ __forceinline__ uint32_t pack_bf16(float lo, float hi) {
    uint32_t d;
    asm("cvt.rn.bf16x2.f32 %0, %1, %2;" : "=r"(d) : "f"(hi), "f"(lo));
    return d;
}
__device__ __forceinline__ float lo_f(uint32_t u) { return __uint_as_float(u << 16); }
__device__ __forceinline__ float hi_f(uint32_t u) { return __uint_as_float(u & 0xffff0000u); }

#define CP16(dst, src) asm volatile("cp.async.ca.shared.global [%0], [%1], 16;" :: "r"(dst), "l"(src))
#define CP_COMMIT()    asm volatile("cp.async.commit_group;")
#define CP_WAIT0()     asm volatile("cp.async.wait_group 0;")
#define CP_WAIT1()     asm volatile("cp.async.wait_group 1;")

// ---------------------------------------------------------------------------
// Kernel 0: fp32 -> bf16 hi + bf16 lo split for x and Wq/Wk/Wv
// ---------------------------------------------------------------------------
#define NX4 (M_*C_/4)
#define NW4 (C_*C_/4)
#define NT4 (NX4 + 3*NW4)

__global__ void __launch_bounds__(256) split_kernel(
    const float* __restrict__ x,  const float* __restrict__ Wq,
    const float* __restrict__ Wk, const float* __restrict__ Wv)
{
    int i4 = blockIdx.x * 256 + threadIdx.x;
    if (i4 >= NT4) return;
    const float* src; __nv_bfloat16 *dh, *dl; size_t off4;
    if (i4 < NX4) { src = x; dh = g_xh; dl = g_xl; off4 = i4; }
    else {
        int j = i4 - NX4;
        int w = j / NW4; off4 = j - w * NW4;
        src = (w == 0) ? Wq : (w == 1) ? Wk : Wv;
        dh = g_wh + (size_t)w * C_ * C_;
        dl = g_wl + (size_t)w * C_ * C_;
    }
    float4 v = ((const float4*)src)[off4];
    uint32_t h01 = pack_bf16(v.x, v.y);
    uint32_t h23 = pack_bf16(v.z, v.w);
    uint32_t l01 = pack_bf16(v.x - lo_f(h01), v.y - hi_f(h01));
    uint32_t l23 = pack_bf16(v.z - lo_f(h23), v.w - hi_f(h23));
    uint32_t* ph = (uint32_t*)(dh + 4*off4);
    uint32_t* pl = (uint32_t*)(dl + 4*off4);
    ph[0] = h01; ph[1] = h23;
    pl[0] = l01; pl[1] = l23;
}

// ---------------------------------------------------------------------------
// Kernel 1: y = x @ W^T + b via HMMA bf16 split, cp.async double-buffered.
// CTA tile 128x128, BK=32, 2 smem stages. Epilogue writes bf16 hi/lo q/k/v.
// ---------------------------------------------------------------------------
#define BK_ 32
#define PADK 40
#define QKVS (4*128*PADK)      // elements per stage (4 arrays)
#define SM_QKV (2*QKVS*2)      // 81920 bytes

__global__ void __launch_bounds__(256, 2) qkv_hmma_kernel(
    const float* __restrict__ bq, const float* __restrict__ bk2,
    const float* __restrict__ bv)
{
    extern __shared__ __nv_bfloat16 smq[];
    __shared__ float sbias[128];

    const int tid  = threadIdx.x;
    const int lane = tid & 31;
    const int wid  = tid >> 5;
    const int z    = blockIdx.z;
    const int m0   = blockIdx.y * 128;
    const int n0   = blockIdx.x * 128;

    const float* bias = (z == 0) ? bq : (z == 1) ? bk2 : bv;
    __nv_bfloat16* dh = (z == 0) ? g_qh : (z == 1) ? g_kh : g_vh;
    __nv_bfloat16* dl = (z == 0) ? g_ql : (z == 1) ? g_kl : g_vl;
    const __nv_bfloat16* wh = g_wh + (size_t)z * C_ * C_;
    const __nv_bfloat16* wl = g_wl + (size_t)z * C_ * C_;

    if (tid < 128) sbias[tid] = bias[n0 + tid];

    const int wm = (wid & 1) * 64;
    const int wn = (wid >> 1) * 32;
    const int lrow = tid >> 1;
    const int lk   = (tid & 1) * 16;

    const uint32_t sb = smem_u32(smq);
    // per-thread fill source rows
    const __nv_bfloat16* srcA_h = g_xh + (size_t)(m0 + lrow) * C_ + lk;
    const __nv_bfloat16* srcA_l = g_xl + (size_t)(m0 + lrow) * C_ + lk;
    const __nv_bfloat16* srcB_h = wh   + (size_t)(n0 + lrow) * C_ + lk;
    const __nv_bfloat16* srcB_l = wl   + (size_t)(n0 + lrow) * C_ + lk;
    const uint32_t dthr = (uint32_t)(lrow*PADK + lk) * 2;   // in-array byte off

    auto issue = [&](int it, int s) {
        const int k0 = it * BK_;
        uint32_t d = sb + (uint32_t)(s*QKVS*2) + dthr;
        const char* a_h = (const char*)(srcA_h + k0);
        const char* a_l = (const char*)(srcA_l + k0);
        const char* b_h = (const char*)(srcB_h + k0);
        const char* b_l = (const char*)(srcB_l + k0);
        CP16(d,                 a_h);      CP16(d + 16,                 a_h + 16);
        CP16(d + 10240,         a_l);      CP16(d + 10240 + 16,         a_l + 16);
        CP16(d + 2*10240,       b_h);      CP16(d + 2*10240 + 16,       b_h + 16);
        CP16(d + 3*10240,       b_l);      CP16(d + 3*10240 + 16,       b_l + 16);
    };

    float acc[4][4][4];
    #pragma unroll
    for (int mt = 0; mt < 4; mt++)
        #pragma unroll
        for (int nt = 0; nt < 4; nt++)
            acc[mt][nt][0] = acc[mt][nt][1] = acc[mt][nt][2] = acc[mt][nt][3] = 0.f;

    issue(0, 0); CP_COMMIT();

    for (int it = 0; it < 32; it++) {
        const int s = it & 1;
        if (it < 31) { issue(it + 1, s ^ 1); CP_COMMIT(); CP_WAIT1(); }
        else         { CP_WAIT0(); }
        __syncthreads();

        const __nv_bfloat16* Ash = smq + s*QKVS;
        const __nv_bfloat16* Asl = Ash + 128*PADK;
        const __nv_bfloat16* Bsh = Asl + 128*PADK;
        const __nv_bfloat16* Bsl = Bsh + 128*PADK;

        #pragma unroll
        for (int ks = 0; ks < 2; ks++) {
            const int kc = ks*16 + (lane & 3)*2;
            const int fr = lane >> 2;

            uint32_t bh[4][2], bl[4][2];
            #pragma unroll
            for (int nt = 0; nt < 4; nt++) {
                int nr = wn + nt*8 + fr;
                bh[nt][0] = *(const uint32_t*)&Bsh[nr*PADK + kc];
                bh[nt][1] = *(const uint32_t*)&Bsh[nr*PADK + kc + 8];
                bl[nt][0] = *(const uint32_t*)&Bsl[nr*PADK + kc];
                bl[nt][1] = *(const uint32_t*)&Bsl[nr*PADK + kc + 8];
            }
            uint32_t ah[4][4], al[4][4];
            #pragma unroll
            for (int mt = 0; mt < 4; mt++) {
                int mr = wm + mt*16 + fr;
                ah[mt][0] = *(const uint32_t*)&Ash[mr*PADK + kc];
                ah[mt][1] = *(const uint32_t*)&Ash[(mr+8)*PADK + kc];
                ah[mt][2] = *(const uint32_t*)&Ash[mr*PADK + kc + 8];
                ah[mt][3] = *(const uint32_t*)&Ash[(mr+8)*PADK + kc + 8];
                al[mt][0] = *(const uint32_t*)&Asl[mr*PADK + kc];
                al[mt][1] = *(const uint32_t*)&Asl[(mr+8)*PADK + kc];
                al[mt][2] = *(const uint32_t*)&Asl[mr*PADK + kc + 8];
                al[mt][3] = *(const uint32_t*)&Asl[(mr+8)*PADK + kc + 8];
            }
            #pragma unroll
            for (int mt = 0; mt < 4; mt++)
                #pragma unroll
                for (int nt = 0; nt < 4; nt++) {
                    mma16816(acc[mt][nt], ah[mt], bh[nt]);
                    mma16816(acc[mt][nt], ah[mt], bl[nt]);
                    mma16816(acc[mt][nt], al[mt], bh[nt]);
                }
        }
        __syncthreads();
    }

    const float scale = (z == 0) ? 0.125f : 1.0f;
    #pragma unroll
    for (int mt = 0; mt < 4; mt++) {
        int grow = m0 + wm + mt*16 + (lane >> 2);
        #pragma unroll
        for (int nt = 0; nt < 4; nt++) {
            int lcol = wn + nt*8 + (lane & 3)*2;
            float bx = sbias[lcol], by = sbias[lcol + 1];
            float y00 = (acc[mt][nt][0] + bx) * scale;
            float y01 = (acc[mt][nt][1] + by) * scale;
            float y10 = (acc[mt][nt][2] + bx) * scale;
            float y11 = (acc[mt][nt][3] + by) * scale;
            size_t o0 = (size_t)grow * C_ + n0 + lcol;
            size_t o1 = (size_t)(grow + 8) * C_ + n0 + lcol;
            uint32_t h0 = pack_bf16(y00, y01);
            uint32_t l0r = pack_bf16(y00 - lo_f(h0), y01 - hi_f(h0));
            uint32_t h1 = pack_bf16(y10, y11);
            uint32_t l1r = pack_bf16(y10 - lo_f(h1), y11 - hi_f(h1));
            *(uint32_t*)&dh[o0] = h0;  *(uint32_t*)&dl[o0] = l0r;
            *(uint32_t*)&dh[o1] = h1;  *(uint32_t*)&dl[o1] = l1r;
        }
    }
}

// ---------------------------------------------------------------------------
// Kernel 2: HMMA flash attention, cp.async double-buffered K/V.
// CTA = (b,h) x 128 q-rows, 8 warps x 16 rows; P stays in registers.
// ---------------------------------------------------------------------------
#define PAD 72
#define QSZ (2*128*PAD)            // Q hi+lo elements
#define KVS (4*64*PAD)             // per-stage elements (Kh,Kl,Vh,Vl)
#define SM_ATTN ((QSZ + 2*KVS)*2)  // 110592 bytes

__global__ void __launch_bounds__(256) attn_kernel(float* __restrict__ out)
{
    extern __shared__ __nv_bfloat16 smb[];
    __nv_bfloat16* Qh = smb;
    __nv_bfloat16* Ql = smb + 128*PAD;

    const int tid  = threadIdx.x;
    const int lane = tid & 31;
    const int w    = tid >> 5;
    const int bh   = blockIdx.y;
    const int b    = bh >> 4, h = bh & 15;
    const int i0   = blockIdx.x * 128;

    // ---- Q tile fill (once, plain loads) ----
    {
        int r = tid >> 1;
        int half = (tid & 1) * 32;
        const uint4* sh = (const uint4*)(g_qh + (size_t)(b*T_ + i0 + r)*C_ + h*D_ + half);
        const uint4* sl = (const uint4*)(g_ql + (size_t)(b*T_ + i0 + r)*C_ + h*D_ + half);
        uint4* dhp = (uint4*)&Qh[r*PAD + half];
        uint4* dlp = (uint4*)&Ql[r*PAD + half];
        #pragma unroll
        for (int g = 0; g < 4; g++) { dhp[g] = sh[g]; dlp[g] = sl[g]; }
    }

    const uint32_t sb  = smem_u32(smb);
    const uint32_t sQh = sb, sQl = sb + 128*PAD*2;

    // ldmatrix lane offsets (bytes, relative to each array base)
    const uint32_t qoff = (uint32_t)(((16*w + (lane & 15))*PAD + (lane >> 4)*8) * 2);
    const uint32_t koff = (uint32_t)((((lane & 7) + ((lane >> 4) & 1)*8)*PAD
                                      + ((lane >> 3) & 1)*8) * 2);
    const uint32_t voff = (uint32_t)((((lane & 7) + ((lane >> 3) & 1)*8)*PAD
                                      + (lane >> 4)*8) * 2);

    float oacc[8][4];
    #pragma unroll
    for (int i = 0; i < 8; i++)
        oacc[i][0] = oacc[i][1] = oacc[i][2] = oacc[i][3] = 0.f;
    float m0 = -1e30f, m1 = -1e30f, l0 = 0.f, l1 = 0.f;

    // K/V fill: one array per warp-pair, one row per thread
    const int kvarr = tid >> 6;
    const int kvrow = tid & 63;
    const __nv_bfloat16* gsrc = (kvarr==0) ? g_kh : (kvarr==1) ? g_kl
                               : (kvarr==2) ? g_vh : g_vl;
    const size_t gbase = (size_t)(b*T_)*C_ + h*D_;
    const uint32_t kvdst0 = sb + (uint32_t)((QSZ + kvarr*64*PAD + kvrow*PAD) * 2);

    auto issue = [&](int jt, int s) {
        uint32_t d = kvdst0 + (uint32_t)(s*KVS*2);
        const char* g = (const char*)(gsrc + gbase + (size_t)(jt*64 + kvrow)*C_);
        #pragma unroll
        for (int gg = 0; gg < 8; gg++) CP16(d + gg*16, g + gg*16);
    };

    issue(0, 0); CP_COMMIT();

    for (int jt = 0; jt < 32; jt++) {
        const int s = jt & 1;
        if (jt < 31) { issue(jt + 1, s ^ 1); CP_COMMIT(); CP_WAIT1(); }
        else         { CP_WAIT0(); }
        __syncthreads();

        const uint32_t sKh = sb + (uint32_t)((QSZ + s*KVS) * 2);
        const uint32_t sKl = sKh + 64*PAD*2;
        const uint32_t sVh = sKl + 64*PAD*2;
        const uint32_t sVl = sVh + 64*PAD*2;

        // ---- S = Q K^T (hi/lo split, fp32 accum) ----
        float sacc[8][4];
        #pragma unroll
        for (int i = 0; i < 8; i++)
            sacc[i][0] = sacc[i][1] = sacc[i][2] = sacc[i][3] = 0.f;

        #pragma unroll
        for (int kc = 0; kc < 4; kc++) {
            uint32_t aqh[4], aql[4];
            ldsm4(aqh, sQh + qoff + kc*32);
            ldsm4(aql, sQl + qoff + kc*32);
            #pragma unroll
            for (int ntp = 0; ntp < 4; ntp++) {
                uint32_t bkh[4], bkl[4];
                uint32_t ko = koff + (uint32_t)(ntp*(16*PAD*2) + kc*32);
                ldsm4(bkh, sKh + ko);
                ldsm4(bkl, sKl + ko);
                mma16816(sacc[2*ntp],   aqh, bkh);
                mma16816(sacc[2*ntp],   aqh, bkl);
                mma16816(sacc[2*ntp],   aql, bkh);
                mma16816(sacc[2*ntp+1], aqh, bkh+2);
                mma16816(sacc[2*ntp+1], aqh, bkl+2);
                mma16816(sacc[2*ntp+1], aql, bkh+2);
            }
        }

        // ---- online softmax ----
        float rm0 = -1e30f, rm1 = -1e30f;
        #pragma unroll
        for (int nt = 0; nt < 8; nt++) {
            rm0 = fmaxf(rm0, fmaxf(sacc[nt][0], sacc[nt][1]));
            rm1 = fmaxf(rm1, fmaxf(sacc[nt][2], sacc[nt][3]));
        }
        rm0 = fmaxf(rm0, __shfl_xor_sync(0xffffffffu, rm0, 1));
        rm0 = fmaxf(rm0, __shfl_xor_sync(0xffffffffu, rm0, 2));
        rm1 = fmaxf(rm1, __shfl_xor_sync(0xffffffffu, rm1, 1));
        rm1 = fmaxf(rm1, __shfl_xor_sync(0xffffffffu, rm1, 2));
        float mn0 = fmaxf(m0, rm0), mn1 = fmaxf(m1, rm1);
        float al0 = __expf(m0 - mn0), al1 = __expf(m1 - mn1);
        m0 = mn0; m1 = mn1;
        float rs0 = 0.f, rs1 = 0.f;
        #pragma unroll
        for (int nt = 0; nt < 8; nt++) {
            sacc[nt][0] = __expf(sacc[nt][0] - mn0);
            sacc[nt][1] = __expf(sacc[nt][1] - mn0);
            sacc[nt][2] = __expf(sacc[nt][2] - mn1);
            sacc[nt][3] = __expf(sacc[nt][3] - mn1);
            rs0 += sacc[nt][0] + sacc[nt][1];
            rs1 += sacc[nt][2] + sacc[nt][3];
        }
        rs0 += __shfl_xor_sync(0xffffffffu, rs0, 1);
        rs0 += __shfl_xor_sync(0xffffffffu, rs0, 2);
        rs1 += __shfl_xor_sync(0xffffffffu, rs1, 1);
        rs1 += __shfl_xor_sync(0xffffffffu, rs1, 2);
        l0 = l0*al0 + rs0;
        l1 = l1*al1 + rs1;
        #pragma unroll
        for (int nt = 0; nt < 8; nt++) {
            oacc[nt][0] *= al0; oacc[nt][1] *= al0;
            oacc[nt][2] *= al1; oacc[nt][3] *= al1;
        }

        // ---- O += P V (P hi/lo rebuilt in registers) ----
        #pragma unroll
        for (int kc = 0; kc < 4; kc++) {
            uint32_t aph[4], apl[4];
            {
                float x0 = sacc[2*kc][0],   x1 = sacc[2*kc][1];
                float x2 = sacc[2*kc][2],   x3 = sacc[2*kc][3];
                float y0 = sacc[2*kc+1][0], y1 = sacc[2*kc+1][1];
                float y2 = sacc[2*kc+1][2], y3 = sacc[2*kc+1][3];
                aph[0] = pack_bf16(x0, x1);
                aph[1] = pack_bf16(x2, x3);
                aph[2] = pack_bf16(y0, y1);
                aph[3] = pack_bf16(y2, y3);
                apl[0] = pack_bf16(x0 - lo_f(aph[0]), x1 - hi_f(aph[0]));
                apl[1] = pack_bf16(x2 - lo_f(aph[1]), x3 - hi_f(aph[1]));
                apl[2] = pack_bf16(y0 - lo_f(aph[2]), y1 - hi_f(aph[2]));
                apl[3] = pack_bf16(y2 - lo_f(aph[3]), y3 - hi_f(aph[3]));
            }
            #pragma unroll
            for (int ntp = 0; ntp < 4; ntp++) {
                uint32_t bvh[4], bvl[4];
                uint32_t vo = voff + (uint32_t)(kc*(16*PAD*2) + ntp*32);
                ldsm4t(bvh, sVh + vo);
                ldsm4t(bvl, sVl + vo);
                mma16816(oacc[2*ntp],   aph, bvh);
                mma16816(oacc[2*ntp],   aph, bvl);
                mma16816(oacc[2*ntp],   apl, bvh);
                mma16816(oacc[2*ntp+1], aph, bvh+2);
                mma16816(oacc[2*ntp+1], aph, bvl+2);
                mma16816(oacc[2*ntp+1], apl, bvh+2);
            }
        }
        __syncthreads();
    }

    // ---- epilogue ----
    float inv0 = 1.0f / l0, inv1 = 1.0f / l1;
    int r = 16*w + (lane >> 2);
    float* o0 = out + (size_t)(b*T_ + i0 + r)*C_ + h*D_ + (lane & 3)*2;
    float* o1 = o0 + 8*C_;
    #pragma unroll
    for (int nt = 0; nt < 8; nt++) {
        *(float2*)(o0 + nt*8) = make_float2(oacc[nt][0]*inv0, oacc[nt][1]*inv0);
        *(float2*)(o1 + nt*8) = make_float2(oacc[nt][2]*inv1, oacc[nt][3]*inv1);
    }
}

extern "C" void kernel_launch(void* const* d_in, const int* in_sizes, int n_in,
                              void* d_out, int out_size)
{
    const float* qx = (const float*)d_in[0];
    const float* Wq = (const float*)d_in[1];
    const float* bq = (const float*)d_in[2];
    const float* Wk = (const float*)d_in[3];
    const float* bk = (const float*)d_in[4];
    const float* Wv = (const float*)d_in[5];
    const float* bv = (const float*)d_in[6];
    float* out = (float*)d_out;

    cudaFuncSetAttribute(qkv_hmma_kernel,
                         cudaFuncAttributeMaxDynamicSharedMemorySize, SM_QKV);
    cudaFuncSetAttribute(attn_kernel,
                         cudaFuncAttributeMaxDynamicSharedMemorySize, SM_ATTN);

    split_kernel<<<(NT4 + 255)/256, 256>>>(qx, Wq, Wk, Wv);
    qkv_hmma_kernel<<<dim3(C_/128, M_/128, 3), 256, SM_QKV>>>(bq, bk, bv);
    attn_kernel<<<dim3(T_/128, B_*H_), 256, SM_ATTN>>>(out);
}